// round 4
// baseline (speedup 1.0000x reference)
#include <cuda_runtime.h>

// Malvar-He-Cutler demosaic, GB300 (sm_103a). Round 4: smem tile + rolling
// register window. Each thread computes a 4-row x 4-col block; per output row
// only ONE new smem row is loaded (2x LDS.128), bases come from the rolling
// 5-row window. 16 LDS.128/thread vs 40 in round 3.

#define TR 32
#define TC 128
#define SR (TR + 4)    // 36 rows  (halo 2 each side)
#define SC (TC + 8)    // 136 cols (halo 2 each side, float4-multiple)

__device__ __forceinline__ float clip01(float v) {
    return fminf(fmaxf(v, 0.0f), 1.0f);
}
__device__ __forceinline__ int refl(int i, int n) {
    i = (i < 0) ? -i : i;
    return (i >= n) ? (2 * n - 2 - i) : i;
}

__global__ void __launch_bounds__(256, 3)
demosaic_kernel(const float* __restrict__ x, float* __restrict__ out,
                int H, int W)
{
    __shared__ __align__(16) float s[SR][SC];

    const int tid     = threadIdx.x;
    const int tile_c0 = blockIdx.x * TC;
    const int tile_r0 = blockIdx.y * TR;

    // ---- Stage (SR x SC) tile into smem ----
    const int r0 = tile_r0 - 2;
    const int c0 = tile_c0 - 2;   // even -> 8B-aligned global base
    const bool interior = (r0 >= 0) & (r0 + SR <= H) & (c0 >= 0) & (c0 + SC <= W);

    if (interior) {
        const float2* __restrict__ xg =
            reinterpret_cast<const float2*>(x + (size_t)r0 * W + c0);
        const int wv = W >> 1;                 // row stride in float2
        for (int idx = tid; idx < SR * (SC / 2); idx += 256) {
            const int lr = idx / (SC / 2);
            const int lc = idx - lr * (SC / 2);
            *reinterpret_cast<float2*>(&s[lr][2 * lc]) = xg[(size_t)lr * wv + lc];
        }
    } else {
        for (int idx = tid; idx < SR * SC; idx += 256) {
            const int lr = idx / SC;
            const int lc = idx - lr * SC;
            s[lr][lc] = x[(size_t)refl(r0 + lr, H) * W + refl(c0 + lc, W)];
        }
    }
    __syncthreads();

    // ---- Compute: thread = 4 consecutive rows x 4 cols ----
    const int tx   = tid & 31;      // col quad: local out cols 4*tx .. 4*tx+3
    const int ty   = tid >> 5;      // row group: local out rows 4*ty .. 4*ty+3
    const int cb   = 4 * tx;        // smem col of window left edge
    const int row0 = 4 * ty;        // smem row of first window top

    float w[5][8];                  // rolling vertical window

#define LOADROW(dst, rr)                                                     \
    {                                                                        \
        const float4 u = *reinterpret_cast<const float4*>(&s[rr][cb]);       \
        const float4 v = *reinterpret_cast<const float4*>(&s[rr][cb + 4]);   \
        dst[0] = u.x; dst[1] = u.y; dst[2] = u.z; dst[3] = u.w;              \
        dst[4] = v.x; dst[5] = v.y; dst[6] = v.z; dst[7] = v.w;              \
    }

    #pragma unroll
    for (int j = 0; j < 4; ++j) LOADROW(w[j], row0 + j)

    const int gr0 = tile_r0 + row0;
    const int gc  = tile_c0 + cb;
    float* dst_row = out + ((size_t)gr0 * W + gc) * 3;
    const size_t out_stride = (size_t)W * 3;

    #pragma unroll
    for (int k = 0; k < 4; ++k) {
        LOADROW(w[(k + 4) % 5], row0 + 4 + k)

        const float* wa = w[(k + 0) % 5];   // j-2
        const float* wb = w[(k + 1) % 5];   // j-1
        const float* wc = w[(k + 2) % 5];   // j
        const float* wd = w[(k + 3) % 5];   // j+1
        const float* we = w[(k + 4) % 5];   // j+2

        float a[8], b[8], c[8];
        #pragma unroll
        for (int i = 0; i < 8; ++i) {
            a[i] = wa[i] + we[i];
            b[i] = wb[i] + wd[i];
            c[i] = wc[i];
        }

        float o[12];
        #pragma unroll
        for (int p = 0; p < 4; ++p) {
            const int q = p + 2;
            const float cc = c[q], bb = b[q], aa = a[q];
            const float s1 = c[q-1] + c[q+1];
            const float s2 = c[q-2] + c[q+2];
            const float s3 = b[q-1] + b[q+1];
            const float gi  = 0.125f * (4.0f*cc + 2.0f*(bb + s1) - (aa + s2));
            const float rgr = 0.125f * (5.0f*cc + 4.0f*s1 - s2 + 0.5f*aa - s3);
            const float rgv = 0.125f * (5.0f*cc + 4.0f*bb - aa + 0.5f*s2 - s3);
            const float rb  = 0.125f * (6.0f*cc + 2.0f*s3 - 1.5f*(aa + s2));
            float R, G, B;
            if ((k & 1) == 0) {          // even global row (tile_r0, row0 even)
                if ((p & 1) == 0) { R = cc;  G = gi; B = rb;  }   // R site
                else              { R = rgr; G = cc; B = rgv; }   // Gr site
            } else {                      // odd global row
                if ((p & 1) == 0) { R = rgv; G = cc; B = rgr; }   // Gb site
                else              { R = rb;  G = gi; B = cc;  }   // B site
            }
            o[3*p+0] = clip01(R);
            o[3*p+1] = clip01(G);
            o[3*p+2] = clip01(B);
        }

        const int gr = gr0 + k;
        if (gr < H && gc + 4 <= W) {
            // gc multiple of 4 -> float offset gc*3 multiple of 12 -> 16B aligned
            float4* d4 = reinterpret_cast<float4*>(dst_row);
            __stcs(d4 + 0, make_float4(o[0], o[1], o[2],  o[3]));
            __stcs(d4 + 1, make_float4(o[4], o[5], o[6],  o[7]));
            __stcs(d4 + 2, make_float4(o[8], o[9], o[10], o[11]));
        } else if (gr < H) {
            #pragma unroll
            for (int p = 0; p < 4; ++p) {
                if (gc + p < W) {
                    float* q2 = out + ((size_t)gr * W + gc + p) * 3;
                    q2[0] = o[3*p]; q2[1] = o[3*p+1]; q2[2] = o[3*p+2];
                }
            }
        }
        dst_row += out_stride;
    }
#undef LOADROW
}

extern "C" void kernel_launch(void* const* d_in, const int* in_sizes, int n_in,
                              void* d_out, int out_size)
{
    const float* x = (const float*)d_in[0];
    long nx = in_sizes[0];
    if (n_in > 1 && in_sizes[1] > in_sizes[0]) {  // defensive: pick the big tensor as x
        x = (const float*)d_in[1];
        nx = in_sizes[1];
    }

    const int W = 6144;
    const int H = (int)(nx / W);

    dim3 block(256);
    dim3 grid((unsigned)((W + TC - 1) / TC), (unsigned)((H + TR - 1) / TR));

    demosaic_kernel<<<grid, block>>>(x, (float*)d_out, H, W);
}

// round 5
// speedup vs baseline: 1.1745x; 1.1745x over previous
#include <cuda_runtime.h>

// Malvar-He-Cutler demosaic, GB300 (sm_103a). Round 5:
// R3 smem tiling + per-thread 2x4 quads that share one 6-row window via
// vertical-basis accumulation (a,b,c even row / A,B,C odd row).
// 24 LDS.128/thread vs 40 in R3; outputs stored row-at-a-time to cap regs.

#define TR 32
#define TC 128
#define SR (TR + 4)    // 36 rows  (halo 2 each side)
#define SC (TC + 8)    // 136 cols (halo 2 each side, float4-multiple)

__device__ __forceinline__ float clip01(float v) {
    return fminf(fmaxf(v, 0.0f), 1.0f);
}
__device__ __forceinline__ int refl(int i, int n) {
    i = (i < 0) ? -i : i;
    return (i >= n) ? (2 * n - 2 - i) : i;
}

__global__ void __launch_bounds__(256, 3)
demosaic_kernel(const float* __restrict__ x, float* __restrict__ out,
                int H, int W)
{
    __shared__ __align__(16) float s[SR][SC];

    const int tid     = threadIdx.x;
    const int tile_c0 = blockIdx.x * TC;
    const int tile_r0 = blockIdx.y * TR;

    // ---- Stage (SR x SC) tile into smem (same as R3) ----
    const int r0 = tile_r0 - 2;
    const int c0 = tile_c0 - 2;   // even -> 8B-aligned global base
    const bool interior = (r0 >= 0) & (r0 + SR <= H) & (c0 >= 0) & (c0 + SC <= W);

    if (interior) {
        const float2* __restrict__ xg =
            reinterpret_cast<const float2*>(x + (size_t)r0 * W + c0);
        const int wv = W >> 1;                 // row stride in float2
        for (int idx = tid; idx < SR * (SC / 2); idx += 256) {
            const int lr = idx / (SC / 2);
            const int lc = idx - lr * (SC / 2);
            *reinterpret_cast<float2*>(&s[lr][2 * lc]) = xg[(size_t)lr * wv + lc];
        }
    } else {
        for (int idx = tid; idx < SR * SC; idx += 256) {
            const int lr = idx / SC;
            const int lc = idx - lr * SC;
            s[lr][lc] = x[(size_t)refl(r0 + lr, H) * W + refl(c0 + lc, W)];
        }
    }
    __syncthreads();

    // ---- Compute: thread = two 2x4 quads (rows 2rp..2rp+1, cols 4tx..4tx+3) ----
    const int tx = tid & 31;      // col quad
    const int ty = tid >> 5;      // row-pair group
    const int cb = 4 * tx;        // smem col of window left edge (global 4tx-2)

    #pragma unroll
    for (int qq = 0; qq < 2; ++qq) {
        const int rp     = ty + qq * 8;   // row pair index 0..15
        const int sm_top = 2 * rp;        // smem row of window top (global 2rp-2)

        // Vertical bases over 8 cols.
        // Even out row (global 2rp):  a=v0+v4, b=v1+v3, c=v2
        // Odd  out row (global 2rp+1): A=v1+v5, B=v2+v4, C=v3
        float a[8], b[8], c[8], A[8], B[8], C[8];

        #pragma unroll
        for (int j = 0; j < 6; ++j) {
            const float4 u = *reinterpret_cast<const float4*>(&s[sm_top + j][cb]);
            const float4 v = *reinterpret_cast<const float4*>(&s[sm_top + j][cb + 4]);
            const float r[8] = {u.x, u.y, u.z, u.w, v.x, v.y, v.z, v.w};
            #pragma unroll
            for (int i = 0; i < 8; ++i) {
                if (j == 0)      { a[i] = r[i]; }
                else if (j == 1) { b[i] = r[i]; A[i] = r[i]; }
                else if (j == 2) { c[i] = r[i]; B[i] = r[i]; }
                else if (j == 3) { C[i] = r[i]; b[i] += r[i]; }
                else if (j == 4) { a[i] += r[i]; B[i] += r[i]; }
                else             { A[i] += r[i]; }
            }
        }

        const int gc = tile_c0 + cb;

        // ---- Row 0 (even global row) ----
        {
            float o[12];
            #pragma unroll
            for (int p = 0; p < 4; ++p) {
                const int q = p + 2;
                const float cc = c[q], bb = b[q], aa = a[q];
                const float s1 = c[q-1] + c[q+1];
                const float s2 = c[q-2] + c[q+2];
                const float s3 = b[q-1] + b[q+1];
                const float gi  = 0.125f * (4.0f*cc + 2.0f*(bb + s1) - (aa + s2));
                const float rgr = 0.125f * (5.0f*cc + 4.0f*s1 - s2 + 0.5f*aa - s3);
                const float rgv = 0.125f * (5.0f*cc + 4.0f*bb - aa + 0.5f*s2 - s3);
                const float rb  = 0.125f * (6.0f*cc + 2.0f*s3 - 1.5f*(aa + s2));
                float R, G, B;
                if ((p & 1) == 0) { R = cc;  G = gi; B = rb;  }   // R site
                else              { R = rgr; G = cc; B = rgv; }   // Gr site
                o[3*p+0] = clip01(R);
                o[3*p+1] = clip01(G);
                o[3*p+2] = clip01(B);
            }
            const int gr = tile_r0 + 2 * rp;
            if (gr < H && gc + 4 <= W) {
                float4* d4 = reinterpret_cast<float4*>(out + ((size_t)gr * W + gc) * 3);
                __stcs(d4 + 0, make_float4(o[0], o[1], o[2],  o[3]));
                __stcs(d4 + 1, make_float4(o[4], o[5], o[6],  o[7]));
                __stcs(d4 + 2, make_float4(o[8], o[9], o[10], o[11]));
            } else if (gr < H) {
                #pragma unroll
                for (int p = 0; p < 4; ++p)
                    if (gc + p < W) {
                        float* q2 = out + ((size_t)gr * W + gc + p) * 3;
                        q2[0] = o[3*p]; q2[1] = o[3*p+1]; q2[2] = o[3*p+2];
                    }
            }
        }

        // ---- Row 1 (odd global row) ----
        {
            float o[12];
            #pragma unroll
            for (int p = 0; p < 4; ++p) {
                const int q = p + 2;
                const float cc = C[q], bb = B[q], aa = A[q];
                const float s1 = C[q-1] + C[q+1];
                const float s2 = C[q-2] + C[q+2];
                const float s3 = B[q-1] + B[q+1];
                const float gi  = 0.125f * (4.0f*cc + 2.0f*(bb + s1) - (aa + s2));
                const float rgr = 0.125f * (5.0f*cc + 4.0f*s1 - s2 + 0.5f*aa - s3);
                const float rgv = 0.125f * (5.0f*cc + 4.0f*bb - aa + 0.5f*s2 - s3);
                const float rb  = 0.125f * (6.0f*cc + 2.0f*s3 - 1.5f*(aa + s2));
                float R, G, B;
                if ((p & 1) == 0) { R = rgv; G = cc; B = rgr; }   // Gb site
                else              { R = rb;  G = gi; B = cc;  }   // B site
                o[3*p+0] = clip01(R);
                o[3*p+1] = clip01(G);
                o[3*p+2] = clip01(B);
            }
            const int gr = tile_r0 + 2 * rp + 1;
            if (gr < H && gc + 4 <= W) {
                float4* d4 = reinterpret_cast<float4*>(out + ((size_t)gr * W + gc) * 3);
                __stcs(d4 + 0, make_float4(o[0], o[1], o[2],  o[3]));
                __stcs(d4 + 1, make_float4(o[4], o[5], o[6],  o[7]));
                __stcs(d4 + 2, make_float4(o[8], o[9], o[10], o[11]));
            } else if (gr < H) {
                #pragma unroll
                for (int p = 0; p < 4; ++p)
                    if (gc + p < W) {
                        float* q2 = out + ((size_t)gr * W + gc + p) * 3;
                        q2[0] = o[3*p]; q2[1] = o[3*p+1]; q2[2] = o[3*p+2];
                    }
            }
        }
    }
}

extern "C" void kernel_launch(void* const* d_in, const int* in_sizes, int n_in,
                              void* d_out, int out_size)
{
    const float* x = (const float*)d_in[0];
    long nx = in_sizes[0];
    if (n_in > 1 && in_sizes[1] > in_sizes[0]) {  // defensive: pick the big tensor as x
        x = (const float*)d_in[1];
        nx = in_sizes[1];
    }

    const int W = 6144;
    const int H = (int)(nx / W);

    dim3 block(256);
    dim3 grid((unsigned)((W + TC - 1) / TC), (unsigned)((H + TR - 1) / TR));

    demosaic_kernel<<<grid, block>>>(x, (float*)d_out, H, W);
}

// round 6
// speedup vs baseline: 1.5858x; 1.3501x over previous
#include <cuda_runtime.h>
#include <cstdint>

// Malvar-He-Cutler demosaic, GB300 (sm_103a). Round 6:
//  - interior tiles staged with cp.async.bulk (global->smem DMA, mbarrier),
//    removing per-thread LDG/STS wavefronts from the L1 path
//  - one 2x4 quad per thread, 6-row basis accumulation (R2-proven, ~80 regs)
//  - window read as LDS.64 (tile shifted by -4 cols for 16B-aligned DMA rows)

#define TR 16
#define TC 128
#define SR (TR + 4)            // 20 staged rows
#define SC 136                 // staged cols: tile_c0-4 .. tile_c0+131
#define SROW_BYTES (SC * 4)    // 544 (multiple of 16)
#define TILE_BYTES (SR * SROW_BYTES)

__device__ __forceinline__ float clip01(float v) {
    return fminf(fmaxf(v, 0.0f), 1.0f);
}
__device__ __forceinline__ int refl(int i, int n) {
    i = (i < 0) ? -i : i;
    return (i >= n) ? (2 * n - 2 - i) : i;
}
__device__ __forceinline__ unsigned smem_u32(const void* p) {
    return (unsigned)__cvta_generic_to_shared(p);
}

__global__ void __launch_bounds__(256, 3)
demosaic_kernel(const float* __restrict__ x, float* __restrict__ out,
                int H, int W)
{
    __shared__ __align__(128) float s[SR][SC];
    __shared__ __align__(8) unsigned long long mbar;

    const int tid     = threadIdx.x;
    const int tile_c0 = blockIdx.x * TC;
    const int tile_r0 = blockIdx.y * TR;
    const int r0 = tile_r0 - 2;   // first staged global row
    const int c0 = tile_c0 - 4;   // first staged global col (16B-aligned)

    const bool interior = (r0 >= 0) & (r0 + SR <= H) & (c0 >= 0) & (c0 + SC <= W);

    if (interior) {
        if (tid == 0) {
            const unsigned mb = smem_u32(&mbar);
            asm volatile("mbarrier.init.shared.b64 [%0], 1;" :: "r"(mb) : "memory");
            asm volatile("mbarrier.arrive.expect_tx.shared.b64 _, [%0], %1;"
                         :: "r"(mb), "r"((unsigned)TILE_BYTES) : "memory");
            const float* src = x + (size_t)r0 * W + c0;
            unsigned dst = smem_u32(&s[0][0]);
            const unsigned nbytes = SROW_BYTES;
            #pragma unroll
            for (int j = 0; j < SR; ++j) {
                asm volatile(
                    "cp.async.bulk.shared::cta.global.mbarrier::complete_tx::bytes "
                    "[%0], [%1], %2, [%3];"
                    :: "r"(dst), "l"(src), "r"(nbytes), "r"(mb) : "memory");
                dst += SROW_BYTES;
                src += W;
            }
        }
        __syncthreads();  // mbarrier init visible to all waiters
        {
            const unsigned mb = smem_u32(&mbar);
            asm volatile(
                "{\n\t"
                ".reg .pred P;\n\t"
                "WAIT_%=:\n\t"
                "mbarrier.try_wait.parity.acquire.cta.shared::cta.b64 P, [%0], 0, 0x989680;\n\t"
                "@P bra DONE_%=;\n\t"
                "bra WAIT_%=;\n\t"
                "DONE_%=:\n\t"
                "}"
                :: "r"(mb) : "memory");
        }
    } else {
        for (int idx = tid; idx < SR * SC; idx += 256) {
            const int lr = idx / SC;
            const int lc = idx - lr * SC;
            s[lr][lc] = x[(size_t)refl(r0 + lr, H) * W + refl(c0 + lc, W)];
        }
        __syncthreads();
    }

    // ---- Compute: one 2x4 quad per thread ----
    const int tx = tid & 31;          // col quad -> global cols tile_c0+4tx .. +3
    const int ty = tid >> 5;          // row pair -> global rows tile_r0+2ty .. +1
    const int sm_top = 2 * ty;        // smem row of window top (global row - 2)
    const int cb = 4 * tx + 2;        // smem col of window left (global col - 2)

    // Vertical bases over 8 window cols.
    // Even out row: a=v0+v4, b=v1+v3, c=v2.  Odd out row: A=v1+v5, B=v2+v4, Cv=v3.
    float a[8], b[8], c[8], A[8], B[8], Cv[8];

    #pragma unroll
    for (int j = 0; j < 6; ++j) {
        float r[8];
        #pragma unroll
        for (int h = 0; h < 4; ++h) {
            const float2 t = *reinterpret_cast<const float2*>(&s[sm_top + j][cb + 2 * h]);
            r[2 * h]     = t.x;
            r[2 * h + 1] = t.y;
        }
        #pragma unroll
        for (int i = 0; i < 8; ++i) {
            if (j == 0)      { a[i] = r[i]; }
            else if (j == 1) { b[i] = r[i]; A[i] = r[i]; }
            else if (j == 2) { c[i] = r[i]; B[i] = r[i]; }
            else if (j == 3) { Cv[i] = r[i]; b[i] += r[i]; }
            else if (j == 4) { a[i] += r[i]; B[i] += r[i]; }
            else             { A[i] += r[i]; }
        }
    }

    const int gc  = tile_c0 + 4 * tx;
    const int gr0 = tile_r0 + 2 * ty;

    // ---- Row 0 (even global row): R Gr R Gr ----
    {
        float o[12];
        #pragma unroll
        for (int p = 0; p < 4; ++p) {
            const int q = p + 2;
            const float cc = c[q], bb = b[q], aa = a[q];
            const float s1 = c[q-1] + c[q+1];
            const float s2 = c[q-2] + c[q+2];
            const float s3 = b[q-1] + b[q+1];
            const float gi  = 0.125f * (4.0f*cc + 2.0f*(bb + s1) - (aa + s2));
            const float rgr = 0.125f * (5.0f*cc + 4.0f*s1 - s2 + 0.5f*aa - s3);
            const float rgv = 0.125f * (5.0f*cc + 4.0f*bb - aa + 0.5f*s2 - s3);
            const float rb  = 0.125f * (6.0f*cc + 2.0f*s3 - 1.5f*(aa + s2));
            if ((p & 1) == 0) { o[3*p]=clip01(cc);  o[3*p+1]=clip01(gi); o[3*p+2]=clip01(rb);  }
            else              { o[3*p]=clip01(rgr); o[3*p+1]=clip01(cc); o[3*p+2]=clip01(rgv); }
        }
        if (gr0 < H && gc + 4 <= W) {
            float4* d4 = reinterpret_cast<float4*>(out + ((size_t)gr0 * W + gc) * 3);
            __stcs(d4 + 0, make_float4(o[0], o[1], o[2],  o[3]));
            __stcs(d4 + 1, make_float4(o[4], o[5], o[6],  o[7]));
            __stcs(d4 + 2, make_float4(o[8], o[9], o[10], o[11]));
        } else if (gr0 < H) {
            #pragma unroll
            for (int p = 0; p < 4; ++p)
                if (gc + p < W) {
                    float* q2 = out + ((size_t)gr0 * W + gc + p) * 3;
                    q2[0] = o[3*p]; q2[1] = o[3*p+1]; q2[2] = o[3*p+2];
                }
        }
    }

    // ---- Row 1 (odd global row): Gb B Gb B ----
    {
        float o[12];
        #pragma unroll
        for (int p = 0; p < 4; ++p) {
            const int q = p + 2;
            const float cc = Cv[q], bb = B[q], aa = A[q];
            const float s1 = Cv[q-1] + Cv[q+1];
            const float s2 = Cv[q-2] + Cv[q+2];
            const float s3 = B[q-1] + B[q+1];
            const float gi  = 0.125f * (4.0f*cc + 2.0f*(bb + s1) - (aa + s2));
            const float rgr = 0.125f * (5.0f*cc + 4.0f*s1 - s2 + 0.5f*aa - s3);
            const float rgv = 0.125f * (5.0f*cc + 4.0f*bb - aa + 0.5f*s2 - s3);
            const float rb  = 0.125f * (6.0f*cc + 2.0f*s3 - 1.5f*(aa + s2));
            if ((p & 1) == 0) { o[3*p]=clip01(rgv); o[3*p+1]=clip01(cc); o[3*p+2]=clip01(rgr); }
            else              { o[3*p]=clip01(rb);  o[3*p+1]=clip01(gi); o[3*p+2]=clip01(cc);  }
        }
        const int gr1 = gr0 + 1;
        if (gr1 < H && gc + 4 <= W) {
            float4* d4 = reinterpret_cast<float4*>(out + ((size_t)gr1 * W + gc) * 3);
            __stcs(d4 + 0, make_float4(o[0], o[1], o[2],  o[3]));
            __stcs(d4 + 1, make_float4(o[4], o[5], o[6],  o[7]));
            __stcs(d4 + 2, make_float4(o[8], o[9], o[10], o[11]));
        } else if (gr1 < H) {
            #pragma unroll
            for (int p = 0; p < 4; ++p)
                if (gc + p < W) {
                    float* q2 = out + ((size_t)gr1 * W + gc + p) * 3;
                    q2[0] = o[3*p]; q2[1] = o[3*p+1]; q2[2] = o[3*p+2];
                }
        }
    }
}

extern "C" void kernel_launch(void* const* d_in, const int* in_sizes, int n_in,
                              void* d_out, int out_size)
{
    const float* x = (const float*)d_in[0];
    long nx = in_sizes[0];
    if (n_in > 1 && in_sizes[1] > in_sizes[0]) {  // defensive: pick the big tensor as x
        x = (const float*)d_in[1];
        nx = in_sizes[1];
    }

    const int W = 6144;
    const int H = (int)(nx / W);

    dim3 block(256);
    dim3 grid((unsigned)((W + TC - 1) / TC), (unsigned)((H + TR - 1) / TR));

    demosaic_kernel<<<grid, block>>>(x, (float*)d_out, H, W);
}